// round 15
// baseline (speedup 1.0000x reference)
#include <cuda_runtime.h>

#define NF 32
#define WPB 8               // warps per block
#define RPB 16              // rows per block (2 per warp)
#define THREADS 256

// -----------------------------------------------------------------------------
// out[b,2d]   = (1/32) sum_f sin(x[b,f] w_d)
// out[b,2d+1] = (1/32) sum_f cos(x[b,f] w_d),  w_d = 10^(-d/64), v = w^2
// sin_mean = w * Sum_{k=0..7} A_k v^k,  cos_mean = 1 + v * Sum_{k=0..7} B_{k+1} v^k
// 16 coefficients; smem pair k = (A_k, B_{k+1}); one f32x2 Horner per d.
// KEY CHANGE vs R14: results staged in SMEM (STS.128) and drained to GMEM via
// cp.async.bulk (TMA store, 4KB/warp-chunk) -- replaces 65k STG.128 going
// through the L1tex store pipeline (the only path common to all 10 plateaued
// variants) with 8k async bulk ops handled by the TMA engine.
// -----------------------------------------------------------------------------

typedef unsigned long long u64;

__device__ __forceinline__ u64 pk2(float a, float b) {
    u64 r; asm("mov.b64 %0, {%1, %2};" : "=l"(r) : "f"(a), "f"(b)); return r;
}
__device__ __forceinline__ u64 pmul(u64 a, u64 b) {
    u64 r; asm("mul.rn.f32x2 %0, %1, %2;" : "=l"(r) : "l"(a), "l"(b)); return r;
}
__device__ __forceinline__ u64 padd(u64 a, u64 b) {
    u64 r; asm("add.rn.f32x2 %0, %1, %2;" : "=l"(r) : "l"(a), "l"(b)); return r;
}
__device__ __forceinline__ u64 pfma(u64 a, u64 b, u64 c) {
    u64 r; asm("fma.rn.f32x2 %0, %1, %2, %3;" : "=l"(r) : "l"(a), "l"(b), "l"(c)); return r;
}
__device__ __forceinline__ void up2(u64 a, float& x, float& y) {
    asm("mov.b64 {%0, %1}, %2;" : "=f"(x), "=f"(y) : "l"(a));
}
__device__ __forceinline__ unsigned smem_u32(const void* p) {
    unsigned a;
    asm("{ .reg .u64 t; cvta.to.shared.u64 t, %1; cvt.u32.u64 %0, t; }"
        : "=r"(a) : "l"(p));
    return a;
}

#define C32 0.9305720409297f    /* 10^(-1/32) */
#define C64 0.9646616199111f    /* 10^(-1/64) */

// id 0..7: A_k scale; id 8..15: B_{k+1} scale (k = id-8)
__constant__ float KSCALE[16] = {
    (float)( 1.0 / 32.0),
    (float)(-1.0 / (6.0 * 32.0)),
    (float)( 1.0 / (120.0 * 32.0)),
    (float)(-1.0 / (5040.0 * 32.0)),
    (float)( 1.0 / (362880.0 * 32.0)),
    (float)(-1.0 / (39916800.0 * 32.0)),
    (float)( 1.0 / (6227020800.0 * 32.0)),
    (float)(-1.0 / (1307674368000.0 * 32.0)),
    (float)(-1.0 / (2.0 * 32.0)),
    (float)( 1.0 / (24.0 * 32.0)),
    (float)(-1.0 / (720.0 * 32.0)),
    (float)( 1.0 / (40320.0 * 32.0)),
    (float)(-1.0 / (3628800.0 * 32.0)),
    (float)( 1.0 / (479001600.0 * 32.0)),
    (float)(-1.0 / (87178291200.0 * 32.0)),
    (float)( 1.0 / (20922789888000.0 * 32.0))
};

template<int NTERM>
__device__ __forceinline__ u64 horner2(const u64* C, u64 V)
{
    u64 H = C[NTERM - 1];
#pragma unroll
    for (int j = NTERM - 2; j >= 0; --j) H = pfma(V, H, C[j]);
    return H;
}

__global__ void __launch_bounds__(THREADS, 4)
pe_kernel(const float* __restrict__ x, float* __restrict__ out)
{
    // result staging: 16 rows x 512 floats = 32KB; coef: 16 x 16 floats = 1KB
    __shared__ __align__(16) float sres[RPB][512];
    __shared__ __align__(16) float scoef[RPB][16];

    const int tid  = threadIdx.x;
    const int wrp  = tid >> 5;
    const int lane = tid & 31;
    const int row0 = blockIdx.x * RPB;          // block's first global row

    // ===== Phase 1: 16 threads/row (2 rows/warp); 15-shfl reduce-scatter =====
    {
        const int rg  = (wrp << 1) + (lane >> 4);   // row in block 0..15
        const int sub = lane & 15;                  // covers f = 2*sub, 2*sub+1

        float2 xv = *(const float2*)(x + (row0 + rg) * NF + sub * 2);

        // acc[k] = (x^{2k+1}, x^{2k+2}) summed over both elements
        u64 acc[8];
        {
            float xx = xv.x, x2 = xx * xx;
            u64 X2 = pk2(x2, x2);
            u64 T  = pk2(xx, x2);
            acc[0] = T;
#pragma unroll
            for (int k = 1; k < 8; ++k) { T = pmul(T, X2); acc[k] = T; }
        }
        {
            float xx = xv.y, x2 = xx * xx;
            u64 X2 = pk2(x2, x2);
            u64 T  = pk2(xx, x2);
            acc[0] = padd(acc[0], T);
#pragma unroll
            for (int k = 1; k < 8; ++k) { T = pmul(T, X2); acc[k] = padd(acc[k], T); }
        }

        // reduce-scatter over the 16-thread group: 8+4+2+1 = 15 shfl
        const bool b0 = sub & 1;
        float v8[8];
#pragma unroll
        for (int i = 0; i < 8; ++i) {
            float lo, hi; up2(acc[i], lo, hi);      // lo: id i, hi: id 8+i
            float keep = b0 ? hi : lo;
            float send = b0 ? lo : hi;
            v8[i] = keep + __shfl_xor_sync(0xffffffffu, send, 1);
        }
        const bool b1 = sub & 2;
        float v4[4];
#pragma unroll
        for (int i = 0; i < 4; ++i) {
            float keep = b1 ? v8[i + 4] : v8[i];
            float send = b1 ? v8[i]     : v8[i + 4];
            v4[i] = keep + __shfl_xor_sync(0xffffffffu, send, 2);
        }
        const bool b2 = sub & 4;
        float v2[2];
#pragma unroll
        for (int i = 0; i < 2; ++i) {
            float keep = b2 ? v2[0] : v2[0];        // placeholder removed below
            (void)keep;
        }
        {
            float k0 = b2 ? v4[2] : v4[0];
            float s0 = b2 ? v4[0] : v4[2];
            v2[0] = k0 + __shfl_xor_sync(0xffffffffu, s0, 4);
            float k1 = b2 ? v4[3] : v4[1];
            float s1 = b2 ? v4[1] : v4[3];
            v2[1] = k1 + __shfl_xor_sync(0xffffffffu, s1, 4);
        }
        const bool b3 = sub & 8;
        float v1;
        {
            float keep = b3 ? v2[1] : v2[0];
            float send = b3 ? v2[0] : v2[1];
            v1 = keep + __shfl_xor_sync(0xffffffffu, send, 8);
        }

        // every lane owns exactly one id; scale + single STS.32
        const int id   = 8 * (int)b0 + 4 * (int)b1 + 2 * (int)b2 + (int)b3;
        const int slot = (id < 8) ? (2 * id) : (2 * id - 15);
        scoef[rg][slot] = v1 * KSCALE[id];
    }
    __syncwarp();

    // ===== Phase 2: packed Horner, results -> SMEM (STS.128) =================
    {
        const float wa0 = exp2f((float)lane * -0.10381025296523007f); // 10^(-2l/64)
        const float va0 = wa0 * wa0;                                   // 10^(-2l/32)
        const float vb0 = va0 * C32;
        const float wb0 = wa0 * C64;
        const u64 DEC = pk2(0.01f, 0.01f);
        const u64 Va1_0 = pk2(va0, va0), Vb1_0 = pk2(vb0, vb0);

#pragma unroll
        for (int k = 0; k < 2; ++k) {               // 2 rows per warp
            const int rg = (wrp << 1) + k;
            const ulonglong2* Cp = (const ulonglong2*)scoef[rg];
            u64 C[8];
#pragma unroll
            for (int q = 0; q < 4; ++q) {
                ulonglong2 t = Cp[q];
                C[2 * q]     = t.x;
                C[2 * q + 1] = t.y;
            }

            u64 Va1 = Va1_0,          Vb1 = Vb1_0;
            u64 Va2 = pmul(Va1, DEC), Vb2 = pmul(Vb1, DEC);
            u64 Va3 = pmul(Va2, DEC), Vb3 = pmul(Vb2, DEC);

            const float wa1 = wa0,        wb1 = wb0;
            const float wa2 = wa1 * 0.1f, wb2 = wb1 * 0.1f;
            const float wa3 = wa2 * 0.1f, wb3 = wb2 * 0.1f;
            const float wa4 = wa3 * 0.1f, wb4 = wb3 * 0.1f;
            const float va1 = va0,          vb1 = vb0;
            const float va2 = va1 * 0.01f,  vb2 = vb1 * 0.01f;
            const float va3 = va2 * 0.01f,  vb3 = vb2 * 0.01f;
            const float va4 = va3 * 0.01f,  vb4 = vb3 * 0.01f;

            float4* o = (float4*)sres[rg] + lane;   // smem, step stride 32

            u64 H1a = horner2<8>(C, Va1);
            u64 H1b = horner2<8>(C, Vb1);
            u64 H2a = horner2<3>(C, Va2);
            u64 H2b = horner2<3>(C, Vb2);
            u64 H3a = horner2<2>(C, Va3);
            u64 H3b = horner2<2>(C, Vb3);

            {
                float sa, ca, sb, cb;
                up2(H1a, sa, ca); up2(H1b, sb, cb);
                o[0]  = make_float4(wa1 * sa, fmaf(va1, ca, 1.0f),
                                    wb1 * sb, fmaf(vb1, cb, 1.0f));
            }
            {
                float sa, ca, sb, cb;
                up2(H2a, sa, ca); up2(H2b, sb, cb);
                o[32] = make_float4(wa2 * sa, fmaf(va2, ca, 1.0f),
                                    wb2 * sb, fmaf(vb2, cb, 1.0f));
            }
            {
                float sa, ca, sb, cb;
                up2(H3a, sa, ca); up2(H3b, sb, cb);
                o[64] = make_float4(wa3 * sa, fmaf(va3, ca, 1.0f),
                                    wb3 * sb, fmaf(vb3, cb, 1.0f));
            }
            {
                float sa, ca;                       // step 4: single term
                up2(C[0], sa, ca);
                o[96] = make_float4(wa4 * sa, fmaf(va4, ca, 1.0f),
                                    wb4 * sa, fmaf(vb4, ca, 1.0f));
            }
        }
    }

    // ===== Drain: SMEM -> GMEM via async bulk copy (TMA store path) =========
    __syncthreads();
    asm volatile("fence.proxy.async.shared::cta;" ::: "memory");

    if (tid < 8) {
        // chunk tid = rows 2*tid, 2*tid+1 : 4KB contiguous in smem and gmem
        unsigned saddr = smem_u32(&sres[tid * 2][0]);
        float* gdst = out + (size_t)(row0 + tid * 2) * 512;
        asm volatile(
            "cp.async.bulk.global.shared::cta.bulk_group [%0], [%1], %2;"
            :: "l"(gdst), "r"(saddr), "r"(4096u) : "memory");
        asm volatile("cp.async.bulk.commit_group;" ::: "memory");
        asm volatile("cp.async.bulk.wait_group 0;" ::: "memory");
    }
}

extern "C" void kernel_launch(void* const* d_in, const int* in_sizes, int n_in,
                              void* d_out, int out_size)
{
    const float* x = (const float*)d_in[0];
    float* out = (float*)d_out;
    int rows = in_sizes[0] / NF;                 // 16384
    pe_kernel<<<rows / RPB, THREADS>>>(x, out);  // 1024 blocks
}

// round 16
// speedup vs baseline: 1.0424x; 1.0424x over previous
#include <cuda_runtime.h>

#define NF 32
#define RPB 16           // rows per block
#define THREADS 128      // 4 warps; each warp owns 4 rows end-to-end

// -----------------------------------------------------------------------------
// out[b,2d]   = (1/32) sum_f sin(x[b,f] w_d)
// out[b,2d+1] = (1/32) sum_f cos(x[b,f] w_d),  w_d = 10^(-d/64), v = w^2
// sin_mean = w * Sum_{k=0..7} A_k v^k,  cos_mean = Sum_{k=0..8} B_k v^k (B_0=1)
//   A_k = S_{2k+1}(-1)^k/((2k+1)! 32),  B_k = S_{2k}(-1)^k/((2k)! 32)
// Session finding: the kernel is pinned at the chip's store floor (~3.8 TB/s
// effective for the 33.5MB output; 11 structurally different variants all land
// 8.8-10.1us). This variant = fastest measured schedule (R5: 4 rows/warp,
// 8 thr/row phase 1) + 16-coefficient math + cheap-steps-first store order.
// -----------------------------------------------------------------------------

typedef unsigned long long u64;

__device__ __forceinline__ u64 pk2(float a, float b) {
    u64 r; asm("mov.b64 %0, {%1, %2};" : "=l"(r) : "f"(a), "f"(b)); return r;
}
__device__ __forceinline__ u64 pmul(u64 a, u64 b) {
    u64 r; asm("mul.rn.f32x2 %0, %1, %2;" : "=l"(r) : "l"(a), "l"(b)); return r;
}
__device__ __forceinline__ u64 padd(u64 a, u64 b) {
    u64 r; asm("add.rn.f32x2 %0, %1, %2;" : "=l"(r) : "l"(a), "l"(b)); return r;
}
__device__ __forceinline__ void up2(u64 a, float& x, float& y) {
    asm("mov.b64 {%0, %1}, %2;" : "=f"(x), "=f"(y) : "l"(a));
}

#define C32 0.9305720409297f    /* 10^(-1/32) */
#define C64 0.9646616199111f    /* 10^(-1/64) */

// id 0..7 : A_k scale = (-1)^k/((2k+1)! 32)
// id 8..15: B_{k+1} scale = (-1)^(k+1)/((2k+2)! 32), k = id-8
__constant__ float KSCALE[16] = {
    (float)( 1.0 / 32.0),
    (float)(-1.0 / (6.0 * 32.0)),
    (float)( 1.0 / (120.0 * 32.0)),
    (float)(-1.0 / (5040.0 * 32.0)),
    (float)( 1.0 / (362880.0 * 32.0)),
    (float)(-1.0 / (39916800.0 * 32.0)),
    (float)( 1.0 / (6227020800.0 * 32.0)),
    (float)(-1.0 / (1307674368000.0 * 32.0)),
    (float)(-1.0 / (2.0 * 32.0)),
    (float)( 1.0 / (24.0 * 32.0)),
    (float)(-1.0 / (720.0 * 32.0)),
    (float)( 1.0 / (40320.0 * 32.0)),
    (float)(-1.0 / (3628800.0 * 32.0)),
    (float)( 1.0 / (479001600.0 * 32.0)),
    (float)(-1.0 / (87178291200.0 * 32.0)),
    (float)( 1.0 / (20922789888000.0 * 32.0))
};

// scalar dual-chain Horner: A has JS terms, B has JC terms (B[0] = 1 included)
template<int JS, int JC>
__device__ __forceinline__ float4 eval_pair(const float* A, const float* B,
                                            float va, float vb,
                                            float wa, float wb)
{
    float hsa = A[JS - 1], hsb = A[JS - 1];
#pragma unroll
    for (int j = JS - 2; j >= 0; --j) {
        hsa = fmaf(va, hsa, A[j]);
        hsb = fmaf(vb, hsb, A[j]);
    }
    float hca = B[JC - 1], hcb = B[JC - 1];
#pragma unroll
    for (int j = JC - 2; j >= 0; --j) {
        hca = fmaf(va, hca, B[j]);
        hcb = fmaf(vb, hcb, B[j]);
    }
    return make_float4(wa * hsa, hca, wb * hsb, hcb);
}

__global__ void __launch_bounds__(THREADS, 8)
pe_kernel(const float* __restrict__ x, float4* __restrict__ out)
{
    // non-interleaved per-row coef: [0..7] = A_k, [8..15] = B_{k+1}
    __shared__ __align__(16) float scoef[RPB][16];

    const int tid  = threadIdx.x;
    const int wrp  = tid >> 5;
    const int lane = tid & 31;
    const int row0 = blockIdx.x * RPB;

    // ===== Phase 1: 8 threads/row (warp covers its 4 rows); packed powers ====
    {
        const int rg  = tid >> 3;    // row in block 0..15 (= wrp*4 + lane>>3)
        const int sub = lane & 7;    // covers f = 4*sub .. 4*sub+3

        // coalesced: warp reads 4 rows x 128B = 512B contiguous
        float4 xv = *(const float4*)(x + (row0 + rg) * NF + sub * 4);

        // acc[k] = (S_{2k+1}, S_{2k+2}) partials, k = 0..7
        u64 acc[8];
        float xs[4] = {xv.x, xv.y, xv.z, xv.w};
        {
            float xx = xs[0], x2 = xx * xx;
            u64 X2 = pk2(x2, x2);
            u64 T  = pk2(xx, x2);
            acc[0] = T;
#pragma unroll
            for (int k = 1; k < 8; ++k) { T = pmul(T, X2); acc[k] = T; }
        }
#pragma unroll
        for (int e = 1; e < 4; ++e) {
            float xx = xs[e], x2 = xx * xx;
            u64 X2 = pk2(x2, x2);
            u64 T  = pk2(xx, x2);
            acc[0] = padd(acc[0], T);
#pragma unroll
            for (int k = 1; k < 8; ++k) { T = pmul(T, X2); acc[k] = padd(acc[k], T); }
        }

        // reduce-scatter over the 8-thread group: 8+4+2 = 14 shfl
        // ids: 0..7 = S_odd (-> A_k), 8..15 = S_even (-> B_{k+1})
        const bool b0 = sub & 1;
        float v8[8];
#pragma unroll
        for (int i = 0; i < 8; ++i) {
            float lo, hi; up2(acc[i], lo, hi);   // lo: id i, hi: id 8+i
            float keep = b0 ? hi : lo;
            float send = b0 ? lo : hi;
            v8[i] = keep + __shfl_xor_sync(0xffffffffu, send, 1);
        }
        const bool b1 = sub & 2;
        float v4[4];
#pragma unroll
        for (int i = 0; i < 4; ++i) {
            float keep = b1 ? v8[i + 4] : v8[i];
            float send = b1 ? v8[i]     : v8[i + 4];
            v4[i] = keep + __shfl_xor_sync(0xffffffffu, send, 2);
        }
        const bool b2 = sub & 4;
        float v2[2];
#pragma unroll
        for (int i = 0; i < 2; ++i) {
            float keep = b2 ? v4[i + 2] : v4[i];
            float send = b2 ? v4[i]     : v4[i + 2];
            v2[i] = keep + __shfl_xor_sync(0xffffffffu, send, 4);
        }

        // thread owns ids base, base+1 (base = 8*b0 + 4*b1 + 2*b2)
        const int base = 8 * (int)b0 + 4 * (int)b1 + 2 * (int)b2;
        scoef[rg][base]     = v2[0] * KSCALE[base];
        scoef[rg][base + 1] = v2[1] * KSCALE[base + 1];
    }
    __syncwarp();   // producer lanes == consumer lanes: warp-local handoff

    // ===== Phase 2: warp-per-4-rows scalar Horner, cheap steps stored first ==
    {
        // lane covers d = 2*lane (a), 2*lane+1 (b)
        const float wa1 = exp2f((float)lane * -0.10381025296523007f); // 10^(-2l/64)
        const float va1 = wa1 * wa1;                                   // 10^(-2l/32)
        const float vb1 = va1 * C32;
        const float wb1 = wa1 * C64;
        const float wa2 = wa1 * 0.1f,  wb2 = wb1 * 0.1f;
        const float wa3 = wa2 * 0.1f,  wb3 = wb2 * 0.1f;
        const float wa4 = wa3 * 0.1f,  wb4 = wb3 * 0.1f;
        const float va2 = va1 * 0.01f, vb2 = vb1 * 0.01f;
        const float va3 = va2 * 0.01f, vb3 = vb2 * 0.01f;
        const float va4 = va3 * 0.01f, vb4 = vb3 * 0.01f;

#pragma unroll
        for (int k = 0; k < 4; ++k) {
            const int rg = (wrp << 2) + k;
            const float4* cf = (const float4*)scoef[rg];   // 4x LDS.128 bcast
            float4 c0 = cf[0], c1 = cf[1], c2 = cf[2], c3 = cf[3];

            float A[8] = {c0.x, c0.y, c0.z, c0.w, c1.x, c1.y, c1.z, c1.w};
            float B[9] = {1.0f, c2.x, c2.y, c2.z, c2.w, c3.x, c3.y, c3.z, c3.w};

            float4* o = out + (row0 + rg) * 128 + lane;

            // cheap steps first: their bytes enter the store pipe while the
            // expensive step-1 chains compute.
            o[32] = eval_pair<3, 4>(A, B, va2, vb2, wa2, wb2); // d[ 64,128) |t|<=0.50
            o[64] = eval_pair<2, 3>(A, B, va3, vb3, wa3, wb3); // d[128,192) |t|<=0.05
            o[96] = eval_pair<1, 2>(A, B, va4, vb4, wa4, wb4); // d[192,256)
            o[0]  = eval_pair<8, 9>(A, B, va1, vb1, wa1, wb1); // d[  0, 64) |t|<=5.0
        }
    }
}

extern "C" void kernel_launch(void* const* d_in, const int* in_sizes, int n_in,
                              void* d_out, int out_size)
{
    const float* x = (const float*)d_in[0];
    float4* out = (float4*)d_out;
    int rows = in_sizes[0] / NF;                 // 16384
    pe_kernel<<<rows / RPB, THREADS>>>(x, out);  // 1024 blocks
}